// round 8
// baseline (speedup 1.0000x reference)
#include <cuda_runtime.h>
#include <cuda_bf16.h>
#include <cstdint>
#include <math.h>

#define NSTEPS 100
#define NU     128
#define BTOT   200000
#define NTHREADS 256
#define CTA_SAMPLES 128   // two 64-row tiles

// ---------------- SMEM layout ----------------
#define SM_H1A  0
#define SM_H1B  16384
#define SM_H2A  32768
#define SM_H2B  49152
#define SM_F32  65536

// float indices within fA
#define F_W3A   0
#define F_W3B   128
#define F_BE0   256      // [2][128] parity ping-pong
#define F_BE1   512
#define F_BE2   768
#define F_COEF  1024
#define F_INVAS 1124
#define F_BSQ   1224
#define F_B3    1324     // 2 floats (pad to 1328)
#define F_XS    1328     // float2[2 tiles][64] = 256 floats
#define F_PP    1584     // float2[2 tiles][4 warps][64] = 1024 floats
#define F_TOTAL 2608
#define SMEM_TOTAL (SM_F32 + F_TOTAL * 4)   // 75968 bytes

// ---------------- helpers ----------------
static __device__ __forceinline__ uint32_t smem_u32(const void* p) {
    uint32_t a;
    asm("{ .reg .u64 t; cvta.to.shared.u64 t, %1; cvt.u32.u64 %0, t; }" : "=r"(a) : "l"(p));
    return a;
}
static __device__ __forceinline__ uint32_t pack_bf16(float lo, float hi) {
    __nv_bfloat162 h = __floats2bfloat162_rn(lo, hi);
    return *reinterpret_cast<uint32_t*>(&h);
}

#define LDSM4(r0, r1, r2, r3, addr)                                              \
    asm volatile("ldmatrix.sync.aligned.m8n8.x4.shared.b16 {%0,%1,%2,%3}, [%4];" \
                 : "=r"(r0), "=r"(r1), "=r"(r2), "=r"(r3) : "r"(addr))

static __device__ __forceinline__ void mma16816(float c[4],
        uint32_t a0, uint32_t a1, uint32_t a2, uint32_t a3,
        uint32_t b0, uint32_t b1) {
    asm volatile(
        "mma.sync.aligned.m16n8k16.row.col.f32.bf16.bf16.f32 "
        "{%0,%1,%2,%3}, {%4,%5,%6,%7}, {%8,%9}, {%0,%1,%2,%3};"
        : "+f"(c[0]), "+f"(c[1]), "+f"(c[2]), "+f"(c[3])
        : "r"(a0), "r"(a1), "r"(a2), "r"(a3), "r"(b0), "r"(b1));
}
static __device__ __forceinline__ void mma16808(float c[4],
        uint32_t a0, uint32_t a1, uint32_t b0) {
    asm volatile(
        "mma.sync.aligned.m16n8k8.row.col.f32.bf16.bf16.f32 "
        "{%0,%1,%2,%3}, {%4,%5}, {%6}, {%0,%1,%2,%3};"
        : "+f"(c[0]), "+f"(c[1]), "+f"(c[2]), "+f"(c[3])
        : "r"(a0), "r"(a1), "r"(b0));
}

static __device__ __forceinline__ void sts32(uint32_t addr, uint32_t v) {
    asm volatile("st.shared.b32 [%0], %1;" :: "r"(addr), "r"(v) : "memory");
}
#define BAR_WG0() asm volatile("bar.sync 1, 128;" ::: "memory")
#define BAR_WG1() asm volatile("bar.sync 2, 128;" ::: "memory")

// ---- G1: dst = relu(src @ W + be), 64x128x128, warp owns 32 N-cols.
//      Two m-tiles per inner loop -> 8 independent accumulator chains. ----
static __device__ __forceinline__ void gemm_g1(
    uint32_t srcb, uint32_t dstb, const uint32_t (&B)[4][8][2], const float* be,
    int wg, uint32_t lrowoff, uint32_t r_lo, uint32_t khalf,
    uint32_t erow, uint32_t ecolq)
{
    #pragma unroll 1
    for (int mp = 0; mp < 2; mp++) {
        const uint32_t abase0 = srcb + (uint32_t)(2 * mp) * 4096 + lrowoff;

        float c[8][4];   // [j*4+nt][q], j = m-tile within pair
        #pragma unroll
        for (int u = 0; u < 8; u++)
            #pragma unroll
            for (int q = 0; q < 4; q++) c[u][q] = 0.f;

        #pragma unroll
        for (int kc = 0; kc < 8; kc++) {
            const uint32_t koff = ((((uint32_t)(kc * 2) + khalf) ^ r_lo) << 4);
            uint32_t x0, x1, x2, x3, y0, y1, y2, y3;
            LDSM4(x0, x1, x2, x3, abase0 + koff);
            LDSM4(y0, y1, y2, y3, abase0 + 4096 + koff);
            #pragma unroll
            for (int nt = 0; nt < 4; nt++)
                mma16816(c[nt], x0, x1, x2, x3, B[nt][kc][0], B[nt][kc][1]);
            #pragma unroll
            for (int nt = 0; nt < 4; nt++)
                mma16816(c[4 + nt], y0, y1, y2, y3, B[nt][kc][0], B[nt][kc][1]);
        }

        #pragma unroll
        for (int j = 0; j < 2; j++) {
            const uint32_t row0 = (uint32_t)(2 * mp + j) * 16 + erow;
            const uint32_t dst0 = dstb + row0 * 256;
            #pragma unroll
            for (int nt = 0; nt < 4; nt++) {
                const float* cc = c[j * 4 + nt];
                int col = wg * 32 + nt * 8 + (int)ecolq * 2;
                float bea = be[col], beb = be[col + 1];
                float v0 = fmaxf(cc[0] + bea, 0.f);
                float v1 = fmaxf(cc[1] + beb, 0.f);
                float v2 = fmaxf(cc[2] + bea, 0.f);
                float v3 = fmaxf(cc[3] + beb, 0.f);
                uint32_t chunk = (uint32_t)(wg * 4 + nt);
                uint32_t a0addr = dst0 + ((chunk ^ erow) << 4) + ecolq * 4;
                sts32(a0addr,        pack_bf16(v0, v1));
                sts32(a0addr + 2048, pack_bf16(v2, v3));
            }
        }
    }
}

// ---- L0: h1 = relu(x @ W0 + be0) via m16n8k8, A from fXS registers ----
static __device__ __forceinline__ void layer0_mma(
    const float2* xs, uint32_t dstb, const uint32_t (&B0)[4], const float* be0,
    int wg, int lane, uint32_t erow, uint32_t ecolq)
{
    const bool klane = ((lane & 3) == 0);
    #pragma unroll
    for (int mt = 0; mt < 4; mt++) {
        float c[4][4];
        #pragma unroll
        for (int nt = 0; nt < 4; nt++)
            #pragma unroll
            for (int q = 0; q < 4; q++) c[nt][q] = 0.f;

        int ra = mt * 16 + (lane >> 2);
        uint32_t a0 = 0u, a1 = 0u;
        if (klane) {
            float2 xa = xs[ra];
            float2 xb = xs[ra + 8];
            a0 = pack_bf16(xa.x, xa.y);
            a1 = pack_bf16(xb.x, xb.y);
        }
        #pragma unroll
        for (int nt = 0; nt < 4; nt++)
            mma16808(c[nt], a0, a1, B0[nt]);

        const uint32_t row0 = (uint32_t)mt * 16 + erow;
        const uint32_t dst0 = dstb + row0 * 256;
        #pragma unroll
        for (int nt = 0; nt < 4; nt++) {
            int col = wg * 32 + nt * 8 + (int)ecolq * 2;
            float bea = be0[col], beb = be0[col + 1];
            float v0 = fmaxf(c[nt][0] + bea, 0.f);
            float v1 = fmaxf(c[nt][1] + beb, 0.f);
            float v2 = fmaxf(c[nt][2] + bea, 0.f);
            float v3 = fmaxf(c[nt][3] + beb, 0.f);
            uint32_t chunk = (uint32_t)(wg * 4 + nt);
            uint32_t a0addr = dst0 + ((chunk ^ erow) << 4) + ecolq * 4;
            sts32(a0addr,        pack_bf16(v0, v1));
            sts32(a0addr + 2048, pack_bf16(v2, v3));
        }
    }
}

// ---- G2 + fused layer3 dot: per-warp pred partials -> fPPt (paired m-tiles) ----
static __device__ __forceinline__ void gemm_g2(
    uint32_t srcb, const uint32_t (&B)[4][8][2], const float* be,
    const float* w3a, const float* w3b, float2* fPPt,
    int wg, uint32_t lrowoff, uint32_t r_lo, uint32_t khalf,
    uint32_t erow, uint32_t ecolq)
{
    #pragma unroll 1
    for (int mp = 0; mp < 2; mp++) {
        const uint32_t abase0 = srcb + (uint32_t)(2 * mp) * 4096 + lrowoff;

        float c[8][4];
        #pragma unroll
        for (int u = 0; u < 8; u++)
            #pragma unroll
            for (int q = 0; q < 4; q++) c[u][q] = 0.f;

        #pragma unroll
        for (int kc = 0; kc < 8; kc++) {
            const uint32_t koff = ((((uint32_t)(kc * 2) + khalf) ^ r_lo) << 4);
            uint32_t x0, x1, x2, x3, y0, y1, y2, y3;
            LDSM4(x0, x1, x2, x3, abase0 + koff);
            LDSM4(y0, y1, y2, y3, abase0 + 4096 + koff);
            #pragma unroll
            for (int nt = 0; nt < 4; nt++)
                mma16816(c[nt], x0, x1, x2, x3, B[nt][kc][0], B[nt][kc][1]);
            #pragma unroll
            for (int nt = 0; nt < 4; nt++)
                mma16816(c[4 + nt], y0, y1, y2, y3, B[nt][kc][0], B[nt][kc][1]);
        }

        #pragma unroll
        for (int j = 0; j < 2; j++) {
            float pA0 = 0.f, pA1 = 0.f, pB0 = 0.f, pB1 = 0.f;
            #pragma unroll
            for (int nt = 0; nt < 4; nt++) {
                const float* cc = c[j * 4 + nt];
                int col = wg * 32 + nt * 8 + (int)ecolq * 2;
                float bea = be[col], beb = be[col + 1];
                float wa0 = w3a[col], wa1 = w3a[col + 1];
                float wb0 = w3b[col], wb1 = w3b[col + 1];
                float v0 = fmaxf(cc[0] + bea, 0.f);
                float v1 = fmaxf(cc[1] + beb, 0.f);
                float v2 = fmaxf(cc[2] + bea, 0.f);
                float v3 = fmaxf(cc[3] + beb, 0.f);
                pA0 = fmaf(v0, wa0, fmaf(v1, wa1, pA0));
                pA1 = fmaf(v0, wb0, fmaf(v1, wb1, pA1));
                pB0 = fmaf(v2, wa0, fmaf(v3, wa1, pB0));
                pB1 = fmaf(v2, wb0, fmaf(v3, wb1, pB1));
            }
            pA0 += __shfl_xor_sync(0xffffffffu, pA0, 1);
            pA1 += __shfl_xor_sync(0xffffffffu, pA1, 1);
            pB0 += __shfl_xor_sync(0xffffffffu, pB0, 1);
            pB1 += __shfl_xor_sync(0xffffffffu, pB1, 1);
            pA0 += __shfl_xor_sync(0xffffffffu, pA0, 2);
            pA1 += __shfl_xor_sync(0xffffffffu, pA1, 2);
            pB0 += __shfl_xor_sync(0xffffffffu, pB0, 2);
            pB1 += __shfl_xor_sync(0xffffffffu, pB1, 2);
            if (ecolq == 0) {
                int r = (2 * mp + j) * 16 + (int)erow;
                fPPt[wg * 64 + r]     = make_float2(pA0, pA1);
                fPPt[wg * 64 + r + 8] = make_float2(pB0, pB1);
            }
        }
    }
}

__global__ void __launch_bounds__(NTHREADS, 2)
ddpm_kernel(const float* __restrict__ noise, const float* __restrict__ z,
            const float* __restrict__ W0, const float* __restrict__ b0,
            const float* __restrict__ W1, const float* __restrict__ b1,
            const float* __restrict__ W2, const float* __restrict__ b2,
            const float* __restrict__ W3, const float* __restrict__ b3,
            const float* __restrict__ E0, const float* __restrict__ E1,
            const float* __restrict__ E2, float* __restrict__ out)
{
    extern __shared__ char smem_raw[];
    const uint32_t sb = smem_u32(smem_raw);
    float* fA = (float*)(smem_raw + SM_F32);
    float2* fXS = (float2*)&fA[F_XS];
    float2* fPP = (float2*)&fA[F_PP];

    const int tid  = threadIdx.x;
    const int lane = tid & 31;
    const int wid  = tid >> 5;
    const bool isWG0 = (wid < 4);
    const int wg   = wid & 3;
    const int base = blockIdx.x * CTA_SAMPLES;

    // ---- prologue ----
    if (tid < 128) {
        fA[F_W3A + tid] = W3[2 * tid];
        fA[F_W3B + tid] = W3[2 * tid + 1];
        fA[F_BE0 + tid] = b0[tid] + E0[99 * NU + tid];  // k=0 (t=99), parity 0
        fA[F_BE1 + tid] = b1[tid] + E1[99 * NU + tid];
        fA[F_BE2 + tid] = b2[tid] + E2[99 * NU + tid];
        int smp = base + tid;
        fXS[tid] = (smp < BTOT) ? ((const float2*)noise)[smp] : make_float2(0.f, 0.f);
    }
    if (tid < 2) fA[F_B3 + tid] = b3[tid];
    if (tid == 0) {
        double prod = 1.0;
        for (int t = 0; t < NSTEPS; t++) {
            double xl = -6.0 + 12.0 * (double)t / 99.0;
            double beta = (1.0 / (1.0 + exp(-xl))) * (0.005 - 1e-5) + 1e-5;
            double alpha = 1.0 - beta;
            prod *= alpha;
            fA[F_COEF + t]  = (float)(beta / sqrt(1.0 - prod));
            fA[F_INVAS + t] = (float)(1.0 / sqrt(alpha));
            fA[F_BSQ + t]   = (float)sqrt(beta);
        }
    }

    // ---- weight fragments ----
    uint32_t Bw[4][8][2];
    uint32_t B0f[4] = {0u, 0u, 0u, 0u};
    {
        const float* Wsrc = isWG0 ? W1 : W2;
        const int n0 = wg * 32 + (lane >> 2);
        const int kb2 = (lane & 3) * 2;
        #pragma unroll
        for (int nt = 0; nt < 4; nt++) {
            int n = n0 + nt * 8;
            #pragma unroll
            for (int kc = 0; kc < 8; kc++) {
                int k0 = kc * 16 + kb2;
                Bw[nt][kc][0] = pack_bf16(Wsrc[k0 * NU + n],       Wsrc[(k0 + 1) * NU + n]);
                Bw[nt][kc][1] = pack_bf16(Wsrc[(k0 + 8) * NU + n], Wsrc[(k0 + 9) * NU + n]);
            }
        }
        if (isWG0 && (lane & 3) == 0) {
            #pragma unroll
            for (int nt = 0; nt < 4; nt++) {
                int n = n0 + nt * 8;
                B0f[nt] = pack_bf16(W0[n], W0[NU + n]);
            }
        }
    }

    // per-lane constants
    const uint32_t r_lo    = (uint32_t)(lane & 7);
    const uint32_t half_l  = (uint32_t)((lane >> 3) & 1);
    const uint32_t khalf   = (uint32_t)(lane >> 4);
    const uint32_t lrowoff = (half_l * 8 + r_lo) * 256;
    const uint32_t erow    = (uint32_t)(lane >> 2);
    const uint32_t ecolq   = (uint32_t)(lane & 3);

    __syncthreads();

    // ---- prime: WG0 runs tile b through L0+G1 at k=0 ----
    if (isWG0) {
        layer0_mma(&fXS[64], sb + SM_H1B, B0f, &fA[F_BE0], wg, lane, erow, ecolq);
        BAR_WG0();
        gemm_g1(sb + SM_H1B, sb + SM_H2B, Bw, &fA[F_BE1], wg,
                lrowoff, r_lo, khalf, erow, ecolq);
    }
    __syncthreads();

    // ---- main loop ----
    #pragma unroll 1
    for (int k = 0; k < NSTEPS; k++) {
        const int t    = 99 - k;
        const int par  = k & 1;
        const bool last = (k == NSTEPS - 1);

        // ===== slotA: WG0: L0(a,k)+G1(a,k) ; WG1: G2(b,k)+update(b,k)+prefetch(k+1) =====
        if (isWG0) {
            layer0_mma(&fXS[0], sb + SM_H1A, B0f, &fA[F_BE0 + par * 128],
                       wg, lane, erow, ecolq);
            BAR_WG0();
            gemm_g1(sb + SM_H1A, sb + SM_H2A, Bw, &fA[F_BE1 + par * 128], wg,
                    lrowoff, r_lo, khalf, erow, ecolq);
        } else {
            const int tid2 = tid - 128;
            float2 zv = make_float2(0.f, 0.f);
            int smpB = base + 64 + (tid2 & 63);
            if (tid2 < 64 && smpB < BTOT)
                zv = ((const float2*)z)[(size_t)k * BTOT + smpB];
            float be0v = 0.f, be1v = 0.f, be2v = 0.f;
            if (!last) {
                int tn = t - 1;
                be0v = b0[tid2] + E0[tn * NU + tid2];
                be1v = b1[tid2] + E1[tn * NU + tid2];
                be2v = b2[tid2] + E2[tn * NU + tid2];
            }
            gemm_g2(sb + SM_H2B, Bw, &fA[F_BE2 + par * 128],
                    &fA[F_W3A], &fA[F_W3B], &fPP[256], wg,
                    lrowoff, r_lo, khalf, erow, ecolq);
            if (!last) {
                int pn = (par ^ 1) * 128;
                fA[F_BE0 + pn + tid2] = be0v;
                fA[F_BE1 + pn + tid2] = be1v;
                fA[F_BE2 + pn + tid2] = be2v;
            }
            BAR_WG1();
            if (tid2 < 64) {
                int r = tid2;
                float p0 = fA[F_B3], p1 = fA[F_B3 + 1];
                #pragma unroll
                for (int g = 0; g < 4; g++) {
                    float2 v = fPP[256 + g * 64 + r];
                    p0 += v.x; p1 += v.y;
                }
                float cf = fA[F_COEF + t], ia = fA[F_INVAS + t], bq = fA[F_BSQ + t];
                float2 xv = fXS[64 + r];
                float nx0 = (xv.x - cf * p0) * ia + bq * zv.x;
                float nx1 = (xv.y - cf * p1) * ia + bq * zv.y;
                if (last) {
                    if (smpB < BTOT) ((float2*)out)[smpB] = make_float2(nx0, nx1);
                } else {
                    fXS[64 + r] = make_float2(nx0, nx1);
                }
            }
        }
        __syncthreads();

        // ===== slotB: WG0: L0(b,k+1)+G1(b,k+1) ; WG1: G2(a,k)+update(a,k) =====
        if (isWG0) {
            if (!last) {
                layer0_mma(&fXS[64], sb + SM_H1B, B0f, &fA[F_BE0 + (par ^ 1) * 128],
                           wg, lane, erow, ecolq);
                BAR_WG0();
                gemm_g1(sb + SM_H1B, sb + SM_H2B, Bw, &fA[F_BE1 + (par ^ 1) * 128], wg,
                        lrowoff, r_lo, khalf, erow, ecolq);
            }
        } else {
            const int tid2 = tid - 128;
            float2 zv = make_float2(0.f, 0.f);
            int smpA = base + (tid2 & 63);
            if (tid2 < 64 && smpA < BTOT)
                zv = ((const float2*)z)[(size_t)k * BTOT + smpA];
            gemm_g2(sb + SM_H2A, Bw, &fA[F_BE2 + par * 128],
                    &fA[F_W3A], &fA[F_W3B], &fPP[0], wg,
                    lrowoff, r_lo, khalf, erow, ecolq);
            BAR_WG1();
            if (tid2 < 64) {
                int r = tid2;
                float p0 = fA[F_B3], p1 = fA[F_B3 + 1];
                #pragma unroll
                for (int g = 0; g < 4; g++) {
                    float2 v = fPP[g * 64 + r];
                    p0 += v.x; p1 += v.y;
                }
                float cf = fA[F_COEF + t], ia = fA[F_INVAS + t], bq = fA[F_BSQ + t];
                float2 xv = fXS[r];
                float nx0 = (xv.x - cf * p0) * ia + bq * zv.x;
                float nx1 = (xv.y - cf * p1) * ia + bq * zv.y;
                if (last) {
                    if (smpA < BTOT) ((float2*)out)[smpA] = make_float2(nx0, nx1);
                } else {
                    fXS[r] = make_float2(nx0, nx1);
                }
            }
        }
        __syncthreads();
    }
}

extern "C" void kernel_launch(void* const* d_in, const int* in_sizes, int n_in,
                              void* d_out, int out_size) {
    (void)in_sizes; (void)n_in; (void)out_size;
    const float* noise = (const float*)d_in[0];
    const float* z     = (const float*)d_in[1];
    const float* W0    = (const float*)d_in[2];
    const float* b0    = (const float*)d_in[3];
    const float* W1    = (const float*)d_in[4];
    const float* b1    = (const float*)d_in[5];
    const float* W2    = (const float*)d_in[6];
    const float* b2    = (const float*)d_in[7];
    const float* W3    = (const float*)d_in[8];
    const float* b3    = (const float*)d_in[9];
    const float* E0    = (const float*)d_in[10];
    const float* E1    = (const float*)d_in[11];
    const float* E2    = (const float*)d_in[12];
    float* out = (float*)d_out;

    cudaFuncSetAttribute(ddpm_kernel, cudaFuncAttributeMaxDynamicSharedMemorySize, SMEM_TOTAL);

    dim3 grid((BTOT + CTA_SAMPLES - 1) / CTA_SAMPLES);
    ddpm_kernel<<<grid, NTHREADS, SMEM_TOTAL>>>(noise, z, W0, b0, W1, b1, W2, b2,
                                                W3, b3, E0, E1, E2, out);
}

// round 9
// speedup vs baseline: 1.0133x; 1.0133x over previous
#include <cuda_runtime.h>
#include <cuda_bf16.h>
#include <cstdint>
#include <math.h>

#define NSTEPS 100
#define NU     128
#define BTOT   200000
#define NTHREADS 256
#define CTA_SAMPLES 128   // two 64-row tiles

// ---------------- SMEM layout ----------------
#define SM_H1A  0
#define SM_H1B  16384
#define SM_H2A  32768
#define SM_H2B  49152
#define SM_F32  65536

// float indices within fA
#define F_W3A   0
#define F_W3B   128
#define F_BE0   256      // [2][128] parity ping-pong
#define F_BE1   512
#define F_BE2   768
#define F_COEF  1024
#define F_INVAS 1124
#define F_BSQ   1224
#define F_B3    1324     // 2 floats (pad to 1328)
#define F_XS    1328     // float2[2 tiles][64] = 256 floats
#define F_PP    1584     // float2[2 tiles][4 warps][64] = 1024 floats
#define F_TOTAL 2608
#define SMEM_TOTAL (SM_F32 + F_TOTAL * 4)   // 75968 bytes

// ---------------- named barriers ----------------
// cross-WG (count 256, producer arrives / consumer syncs), parity-indexed:
//   BH2A = 1+p : WG0 G1(a,k) done -> WG1 may G2(a,k)
//   BH2B = 3+p : WG0 G1(b,k) done -> WG1 may G2(b,k)
//   BUA  = 5+p : WG1 update(a,k) done -> WG0 may L0/G1(a,k+1)
//   BUB  = 7+p : WG1 update(b,k) done -> WG0 may L0/G1(b,k+1)
// internal: 9 = WG1 (128), 10 = WG0 (128)
#define BAR_ARRIVE256(id) asm volatile("bar.arrive %0, 256;" :: "r"(id))
#define BAR_WAIT256(id)   asm volatile("bar.sync %0, 256;" :: "r"(id) : "memory")
#define BAR_WG0()         asm volatile("bar.sync 10, 128;" ::: "memory")
#define BAR_WG1()         asm volatile("bar.sync 9, 128;"  ::: "memory")

// ---------------- helpers ----------------
static __device__ __forceinline__ uint32_t smem_u32(const void* p) {
    uint32_t a;
    asm("{ .reg .u64 t; cvta.to.shared.u64 t, %1; cvt.u32.u64 %0, t; }" : "=r"(a) : "l"(p));
    return a;
}
static __device__ __forceinline__ uint32_t pack_bf16(float lo, float hi) {
    __nv_bfloat162 h = __floats2bfloat162_rn(lo, hi);
    return *reinterpret_cast<uint32_t*>(&h);
}

#define LDSM4(r0, r1, r2, r3, addr)                                              \
    asm volatile("ldmatrix.sync.aligned.m8n8.x4.shared.b16 {%0,%1,%2,%3}, [%4];" \
                 : "=r"(r0), "=r"(r1), "=r"(r2), "=r"(r3) : "r"(addr))

static __device__ __forceinline__ void mma16816(float c[4],
        uint32_t a0, uint32_t a1, uint32_t a2, uint32_t a3,
        uint32_t b0, uint32_t b1) {
    asm volatile(
        "mma.sync.aligned.m16n8k16.row.col.f32.bf16.bf16.f32 "
        "{%0,%1,%2,%3}, {%4,%5,%6,%7}, {%8,%9}, {%0,%1,%2,%3};"
        : "+f"(c[0]), "+f"(c[1]), "+f"(c[2]), "+f"(c[3])
        : "r"(a0), "r"(a1), "r"(a2), "r"(a3), "r"(b0), "r"(b1));
}
static __device__ __forceinline__ void mma16808(float c[4],
        uint32_t a0, uint32_t a1, uint32_t b0) {
    asm volatile(
        "mma.sync.aligned.m16n8k8.row.col.f32.bf16.bf16.f32 "
        "{%0,%1,%2,%3}, {%4,%5}, {%6}, {%0,%1,%2,%3};"
        : "+f"(c[0]), "+f"(c[1]), "+f"(c[2]), "+f"(c[3])
        : "r"(a0), "r"(a1), "r"(b0));
}

static __device__ __forceinline__ void sts32(uint32_t addr, uint32_t v) {
    asm volatile("st.shared.b32 [%0], %1;" :: "r"(addr), "r"(v) : "memory");
}

// ---- G1: dst = relu(src @ W + be), 64x128x128 (R6-proven core) ----
static __device__ __forceinline__ void gemm_g1(
    uint32_t srcb, uint32_t dstb, const uint32_t (&B)[4][8][2], const float* be,
    int wg, uint32_t lrowoff, uint32_t r_lo, uint32_t khalf,
    uint32_t erow, uint32_t ecolq)
{
    #pragma unroll 1
    for (int mt = 0; mt < 4; mt++) {
        const uint32_t abase = srcb + (uint32_t)mt * 4096 + lrowoff;

        uint32_t af[8][4];
        #pragma unroll
        for (int kc = 0; kc < 8; kc++)
            LDSM4(af[kc][0], af[kc][1], af[kc][2], af[kc][3],
                  abase + ((((uint32_t)(kc * 2) + khalf) ^ r_lo) << 4));

        float c[4][4];
        #pragma unroll
        for (int nt = 0; nt < 4; nt++)
            #pragma unroll
            for (int q = 0; q < 4; q++) c[nt][q] = 0.f;

        #pragma unroll
        for (int kc = 0; kc < 8; kc++)
            #pragma unroll
            for (int nt = 0; nt < 4; nt++)
                mma16816(c[nt], af[kc][0], af[kc][1], af[kc][2], af[kc][3],
                         B[nt][kc][0], B[nt][kc][1]);

        const uint32_t row0 = (uint32_t)mt * 16 + erow;
        const uint32_t dst0 = dstb + row0 * 256;
        #pragma unroll
        for (int nt = 0; nt < 4; nt++) {
            int col = wg * 32 + nt * 8 + (int)ecolq * 2;
            float bea = be[col], beb = be[col + 1];
            float v0 = fmaxf(c[nt][0] + bea, 0.f);
            float v1 = fmaxf(c[nt][1] + beb, 0.f);
            float v2 = fmaxf(c[nt][2] + bea, 0.f);
            float v3 = fmaxf(c[nt][3] + beb, 0.f);
            uint32_t chunk = (uint32_t)(wg * 4 + nt);
            uint32_t a0addr = dst0 + ((chunk ^ erow) << 4) + ecolq * 4;
            sts32(a0addr,        pack_bf16(v0, v1));
            sts32(a0addr + 2048, pack_bf16(v2, v3));
        }
    }
}

// ---- L0: h1 = relu(x @ W0 + be0) via m16n8k8, A from fXS ----
static __device__ __forceinline__ void layer0_mma(
    const float2* xs, uint32_t dstb, const uint32_t (&B0)[4], const float* be0,
    int wg, int lane, uint32_t erow, uint32_t ecolq)
{
    const bool klane = ((lane & 3) == 0);
    #pragma unroll
    for (int mt = 0; mt < 4; mt++) {
        float c[4][4];
        #pragma unroll
        for (int nt = 0; nt < 4; nt++)
            #pragma unroll
            for (int q = 0; q < 4; q++) c[nt][q] = 0.f;

        int ra = mt * 16 + (lane >> 2);
        uint32_t a0 = 0u, a1 = 0u;
        if (klane) {
            float2 xa = xs[ra];
            float2 xb = xs[ra + 8];
            a0 = pack_bf16(xa.x, xa.y);
            a1 = pack_bf16(xb.x, xb.y);
        }
        #pragma unroll
        for (int nt = 0; nt < 4; nt++)
            mma16808(c[nt], a0, a1, B0[nt]);

        const uint32_t row0 = (uint32_t)mt * 16 + erow;
        const uint32_t dst0 = dstb + row0 * 256;
        #pragma unroll
        for (int nt = 0; nt < 4; nt++) {
            int col = wg * 32 + nt * 8 + (int)ecolq * 2;
            float bea = be0[col], beb = be0[col + 1];
            float v0 = fmaxf(c[nt][0] + bea, 0.f);
            float v1 = fmaxf(c[nt][1] + beb, 0.f);
            float v2 = fmaxf(c[nt][2] + bea, 0.f);
            float v3 = fmaxf(c[nt][3] + beb, 0.f);
            uint32_t chunk = (uint32_t)(wg * 4 + nt);
            uint32_t a0addr = dst0 + ((chunk ^ erow) << 4) + ecolq * 4;
            sts32(a0addr,        pack_bf16(v0, v1));
            sts32(a0addr + 2048, pack_bf16(v2, v3));
        }
    }
}

// ---- G2 + fused layer3 dot -> fPPt ----
static __device__ __forceinline__ void gemm_g2(
    uint32_t srcb, const uint32_t (&B)[4][8][2], const float* be,
    const float* w3a, const float* w3b, float2* fPPt,
    int wg, uint32_t lrowoff, uint32_t r_lo, uint32_t khalf,
    uint32_t erow, uint32_t ecolq)
{
    #pragma unroll 1
    for (int mt = 0; mt < 4; mt++) {
        const uint32_t abase = srcb + (uint32_t)mt * 4096 + lrowoff;

        uint32_t af[8][4];
        #pragma unroll
        for (int kc = 0; kc < 8; kc++)
            LDSM4(af[kc][0], af[kc][1], af[kc][2], af[kc][3],
                  abase + ((((uint32_t)(kc * 2) + khalf) ^ r_lo) << 4));

        float c[4][4];
        #pragma unroll
        for (int nt = 0; nt < 4; nt++)
            #pragma unroll
            for (int q = 0; q < 4; q++) c[nt][q] = 0.f;

        #pragma unroll
        for (int kc = 0; kc < 8; kc++)
            #pragma unroll
            for (int nt = 0; nt < 4; nt++)
                mma16816(c[nt], af[kc][0], af[kc][1], af[kc][2], af[kc][3],
                         B[nt][kc][0], B[nt][kc][1]);

        float pA0 = 0.f, pA1 = 0.f, pB0 = 0.f, pB1 = 0.f;
        #pragma unroll
        for (int nt = 0; nt < 4; nt++) {
            int col = wg * 32 + nt * 8 + (int)ecolq * 2;
            float bea = be[col], beb = be[col + 1];
            float wa0 = w3a[col], wa1 = w3a[col + 1];
            float wb0 = w3b[col], wb1 = w3b[col + 1];
            float v0 = fmaxf(c[nt][0] + bea, 0.f);
            float v1 = fmaxf(c[nt][1] + beb, 0.f);
            float v2 = fmaxf(c[nt][2] + bea, 0.f);
            float v3 = fmaxf(c[nt][3] + beb, 0.f);
            pA0 = fmaf(v0, wa0, fmaf(v1, wa1, pA0));
            pA1 = fmaf(v0, wb0, fmaf(v1, wb1, pA1));
            pB0 = fmaf(v2, wa0, fmaf(v3, wa1, pB0));
            pB1 = fmaf(v2, wb0, fmaf(v3, wb1, pB1));
        }
        pA0 += __shfl_xor_sync(0xffffffffu, pA0, 1);
        pA1 += __shfl_xor_sync(0xffffffffu, pA1, 1);
        pB0 += __shfl_xor_sync(0xffffffffu, pB0, 1);
        pB1 += __shfl_xor_sync(0xffffffffu, pB1, 1);
        pA0 += __shfl_xor_sync(0xffffffffu, pA0, 2);
        pA1 += __shfl_xor_sync(0xffffffffu, pA1, 2);
        pB0 += __shfl_xor_sync(0xffffffffu, pB0, 2);
        pB1 += __shfl_xor_sync(0xffffffffu, pB1, 2);
        if (ecolq == 0) {
            int r = mt * 16 + (int)erow;
            fPPt[wg * 64 + r]     = make_float2(pA0, pA1);
            fPPt[wg * 64 + r + 8] = make_float2(pB0, pB1);
        }
    }
}

__global__ void __launch_bounds__(NTHREADS, 2)
ddpm_kernel(const float* __restrict__ noise, const float* __restrict__ z,
            const float* __restrict__ W0, const float* __restrict__ b0,
            const float* __restrict__ W1, const float* __restrict__ b1,
            const float* __restrict__ W2, const float* __restrict__ b2,
            const float* __restrict__ W3, const float* __restrict__ b3,
            const float* __restrict__ E0, const float* __restrict__ E1,
            const float* __restrict__ E2, float* __restrict__ out)
{
    extern __shared__ char smem_raw[];
    const uint32_t sb = smem_u32(smem_raw);
    float* fA = (float*)(smem_raw + SM_F32);
    float2* fXS = (float2*)&fA[F_XS];
    float2* fPP = (float2*)&fA[F_PP];

    const int tid  = threadIdx.x;
    const int lane = tid & 31;
    const int wid  = tid >> 5;
    const bool isWG0 = (wid < 4);
    const int wg   = wid & 3;
    const int base = blockIdx.x * CTA_SAMPLES;

    // ---- prologue ----
    if (tid < 128) {
        fA[F_W3A + tid] = W3[2 * tid];
        fA[F_W3B + tid] = W3[2 * tid + 1];
        fA[F_BE0 + tid] = b0[tid] + E0[99 * NU + tid];  // k=0 (t=99), parity 0
        fA[F_BE1 + tid] = b1[tid] + E1[99 * NU + tid];
        fA[F_BE2 + tid] = b2[tid] + E2[99 * NU + tid];
        int smp = base + tid;
        fXS[tid] = (smp < BTOT) ? ((const float2*)noise)[smp] : make_float2(0.f, 0.f);
    }
    if (tid < 2) fA[F_B3 + tid] = b3[tid];
    if (tid == 0) {
        double prod = 1.0;
        for (int t = 0; t < NSTEPS; t++) {
            double xl = -6.0 + 12.0 * (double)t / 99.0;
            double beta = (1.0 / (1.0 + exp(-xl))) * (0.005 - 1e-5) + 1e-5;
            double alpha = 1.0 - beta;
            prod *= alpha;
            fA[F_COEF + t]  = (float)(beta / sqrt(1.0 - prod));
            fA[F_INVAS + t] = (float)(1.0 / sqrt(alpha));
            fA[F_BSQ + t]   = (float)sqrt(beta);
        }
    }

    // ---- weight fragments ----
    uint32_t Bw[4][8][2];
    uint32_t B0f[4] = {0u, 0u, 0u, 0u};
    {
        const float* Wsrc = isWG0 ? W1 : W2;
        const int n0 = wg * 32 + (lane >> 2);
        const int kb2 = (lane & 3) * 2;
        #pragma unroll
        for (int nt = 0; nt < 4; nt++) {
            int n = n0 + nt * 8;
            #pragma unroll
            for (int kc = 0; kc < 8; kc++) {
                int k0 = kc * 16 + kb2;
                Bw[nt][kc][0] = pack_bf16(Wsrc[k0 * NU + n],       Wsrc[(k0 + 1) * NU + n]);
                Bw[nt][kc][1] = pack_bf16(Wsrc[(k0 + 8) * NU + n], Wsrc[(k0 + 9) * NU + n]);
            }
        }
        if (isWG0 && (lane & 3) == 0) {
            #pragma unroll
            for (int nt = 0; nt < 4; nt++) {
                int n = n0 + nt * 8;
                B0f[nt] = pack_bf16(W0[n], W0[NU + n]);
            }
        }
    }

    // per-lane constants
    const uint32_t r_lo    = (uint32_t)(lane & 7);
    const uint32_t half_l  = (uint32_t)((lane >> 3) & 1);
    const uint32_t khalf   = (uint32_t)(lane >> 4);
    const uint32_t lrowoff = (half_l * 8 + r_lo) * 256;
    const uint32_t erow    = (uint32_t)(lane >> 2);
    const uint32_t ecolq   = (uint32_t)(lane & 3);

    __syncthreads();

    if (isWG0) {
        // ---- prime: tile b through L0+G1 at k=0 ----
        layer0_mma(&fXS[64], sb + SM_H1B, B0f, &fA[F_BE0], wg, lane, erow, ecolq);
        BAR_WG0();
        gemm_g1(sb + SM_H1B, sb + SM_H2B, Bw, &fA[F_BE1], wg,
                lrowoff, r_lo, khalf, erow, ecolq);
        BAR_ARRIVE256(3);   // BH2B[0]

        #pragma unroll 1
        for (int k = 0; k < NSTEPS; k++) {
            const int p  = k & 1;
            const int pn = p ^ 1;

            if (k > 0) BAR_WAIT256(5 + pn);     // BUA[(k-1)&1]: fXS.a + H2A free
            layer0_mma(&fXS[0], sb + SM_H1A, B0f, &fA[F_BE0 + p * 128],
                       wg, lane, erow, ecolq);
            BAR_WG0();
            gemm_g1(sb + SM_H1A, sb + SM_H2A, Bw, &fA[F_BE1 + p * 128], wg,
                    lrowoff, r_lo, khalf, erow, ecolq);
            BAR_ARRIVE256(1 + p);               // BH2A[p]

            if (k < NSTEPS - 1) {
                BAR_WAIT256(7 + p);             // BUB[p]: fXS.b + H2B free + tables[pn]
                layer0_mma(&fXS[64], sb + SM_H1B, B0f, &fA[F_BE0 + pn * 128],
                           wg, lane, erow, ecolq);
                BAR_WG0();
                gemm_g1(sb + SM_H1B, sb + SM_H2B, Bw, &fA[F_BE1 + pn * 128], wg,
                        lrowoff, r_lo, khalf, erow, ecolq);
                BAR_ARRIVE256(3 + pn);          // BH2B[pn]
            }
        }
    } else {
        const int tid2 = tid - 128;
        const int row  = tid2 & 63;
        const int smpA = base + row;
        const int smpB = base + 64 + row;

        #pragma unroll 1
        for (int k = 0; k < NSTEPS; k++) {
            const int p  = k & 1;
            const int pn = p ^ 1;
            const int t  = 99 - k;
            const bool last = (k == NSTEPS - 1);

            // early global loads (latency hidden under barrier wait + GEMMs)
            float2 zvB = make_float2(0.f, 0.f), zvA = make_float2(0.f, 0.f);
            if (tid2 < 64) {
                if (smpB < BTOT) zvB = ((const float2*)z)[(size_t)k * BTOT + smpB];
                if (smpA < BTOT) zvA = ((const float2*)z)[(size_t)k * BTOT + smpA];
            }
            float be0v = 0.f, be1v = 0.f, be2v = 0.f;
            if (!last) {
                int tn = t - 1;
                be0v = b0[tid2] + E0[tn * NU + tid2];
                be1v = b1[tid2] + E1[tn * NU + tid2];
                be2v = b2[tid2] + E2[tn * NU + tid2];
            }

            // ---- tile b, step k ----
            BAR_WAIT256(3 + p);                 // BH2B[p]
            gemm_g2(sb + SM_H2B, Bw, &fA[F_BE2 + p * 128],
                    &fA[F_W3A], &fA[F_W3B], &fPP[256], wg,
                    lrowoff, r_lo, khalf, erow, ecolq);
            if (!last) {                         // publish k+1 tables (parity pn)
                fA[F_BE0 + pn * 128 + tid2] = be0v;
                fA[F_BE1 + pn * 128 + tid2] = be1v;
                fA[F_BE2 + pn * 128 + tid2] = be2v;
            }
            BAR_WG1();
            if (tid2 < 64) {
                float p0 = fA[F_B3], p1 = fA[F_B3 + 1];
                #pragma unroll
                for (int g = 0; g < 4; g++) {
                    float2 v = fPP[256 + g * 64 + row];
                    p0 += v.x; p1 += v.y;
                }
                float cf = fA[F_COEF + t], ia = fA[F_INVAS + t], bq = fA[F_BSQ + t];
                float2 xv = fXS[64 + row];
                float nx0 = (xv.x - cf * p0) * ia + bq * zvB.x;
                float nx1 = (xv.y - cf * p1) * ia + bq * zvB.y;
                if (last) {
                    if (smpB < BTOT) ((float2*)out)[smpB] = make_float2(nx0, nx1);
                } else {
                    fXS[64 + row] = make_float2(nx0, nx1);
                }
            }
            BAR_ARRIVE256(7 + p);               // BUB[p]

            // ---- tile a, step k ----
            BAR_WAIT256(1 + p);                 // BH2A[p]
            gemm_g2(sb + SM_H2A, Bw, &fA[F_BE2 + p * 128],
                    &fA[F_W3A], &fA[F_W3B], &fPP[0], wg,
                    lrowoff, r_lo, khalf, erow, ecolq);
            BAR_WG1();
            if (tid2 < 64) {
                float p0 = fA[F_B3], p1 = fA[F_B3 + 1];
                #pragma unroll
                for (int g = 0; g < 4; g++) {
                    float2 v = fPP[g * 64 + row];
                    p0 += v.x; p1 += v.y;
                }
                float cf = fA[F_COEF + t], ia = fA[F_INVAS + t], bq = fA[F_BSQ + t];
                float2 xv = fXS[row];
                float nx0 = (xv.x - cf * p0) * ia + bq * zvA.x;
                float nx1 = (xv.y - cf * p1) * ia + bq * zvA.y;
                if (last) {
                    if (smpA < BTOT) ((float2*)out)[smpA] = make_float2(nx0, nx1);
                } else {
                    fXS[row] = make_float2(nx0, nx1);
                }
            }
            BAR_ARRIVE256(5 + p);               // BUA[p]
        }
    }
}

extern "C" void kernel_launch(void* const* d_in, const int* in_sizes, int n_in,
                              void* d_out, int out_size) {
    (void)in_sizes; (void)n_in; (void)out_size;
    const float* noise = (const float*)d_in[0];
    const float* z     = (const float*)d_in[1];
    const float* W0    = (const float*)d_in[2];
    const float* b0    = (const float*)d_in[3];
    const float* W1    = (const float*)d_in[4];
    const float* b1    = (const float*)d_in[5];
    const float* W2    = (const float*)d_in[6];
    const float* b2    = (const float*)d_in[7];
    const float* W3    = (const float*)d_in[8];
    const float* b3    = (const float*)d_in[9];
    const float* E0    = (const float*)d_in[10];
    const float* E1    = (const float*)d_in[11];
    const float* E2    = (const float*)d_in[12];
    float* out = (float*)d_out;

    cudaFuncSetAttribute(ddpm_kernel, cudaFuncAttributeMaxDynamicSharedMemorySize, SMEM_TOTAL);

    dim3 grid((BTOT + CTA_SAMPLES - 1) / CTA_SAMPLES);
    ddpm_kernel<<<grid, NTHREADS, SMEM_TOTAL>>>(noise, z, W0, b0, W1, b1, W2, b2,
                                                W3, b3, E0, E1, E2, out);
}

// round 10
// speedup vs baseline: 1.1772x; 1.1618x over previous
#include <cuda_runtime.h>
#include <cuda_bf16.h>
#include <cstdint>
#include <math.h>

#define NSTEPS 100
#define NU     128
#define BTOT   200000
#define NTHREADS 256
#define NTILES   3
#define CTA_SAMPLES 192   // three 64-row tiles

// ---------------- SMEM layout ----------------
// H1[i] at i*16384, H2[i] at 49152 + i*16384, floats at 98304
#define SM_H1   0
#define SM_H2   49152
#define SM_F32  98304

// float indices within fA
#define F_W3A   0
#define F_W3B   128
#define F_BE0   256      // [2][128] parity ping-pong
#define F_BE1   512
#define F_BE2   768
#define F_COEF  1024
#define F_INVAS 1124
#define F_BSQ   1224
#define F_B3    1324     // 2 floats (pad to 1328)
#define F_XS    1328     // float2[3 tiles][64] = 384 floats
#define F_PP    1712     // float2[3 tiles][4 warps][64] = 1536 floats
#define F_TOTAL 3248
#define SMEM_TOTAL (SM_F32 + F_TOTAL * 4)   // 111296 bytes; x2 CTA = 222592 <= 228KB

// ---------------- named barriers ----------------
//   BH2[i][p] = 1 + i*2 + p  : WG0 G1(tile i, step k) done -> WG1 may G2
//   BU[i][p]  = 7 + i*2 + p  : WG1 update(tile i, step k) done -> WG0 may L0/G1(k+1)
//   13 = WG0 internal (128), 14 = WG1 internal (128)
#define BAR_ARRIVE256(id) asm volatile("bar.arrive %0, 256;" :: "r"(id))
#define BAR_WAIT256(id)   asm volatile("bar.sync %0, 256;" :: "r"(id) : "memory")
#define BAR_WG0()         asm volatile("bar.sync 13, 128;" ::: "memory")
#define BAR_WG1()         asm volatile("bar.sync 14, 128;" ::: "memory")

// ---------------- helpers ----------------
static __device__ __forceinline__ uint32_t smem_u32(const void* p) {
    uint32_t a;
    asm("{ .reg .u64 t; cvta.to.shared.u64 t, %1; cvt.u32.u64 %0, t; }" : "=r"(a) : "l"(p));
    return a;
}
static __device__ __forceinline__ uint32_t pack_bf16(float lo, float hi) {
    __nv_bfloat162 h = __floats2bfloat162_rn(lo, hi);
    return *reinterpret_cast<uint32_t*>(&h);
}

#define LDSM4(r0, r1, r2, r3, addr)                                              \
    asm volatile("ldmatrix.sync.aligned.m8n8.x4.shared.b16 {%0,%1,%2,%3}, [%4];" \
                 : "=r"(r0), "=r"(r1), "=r"(r2), "=r"(r3) : "r"(addr))

static __device__ __forceinline__ void mma16816(float c[4],
        uint32_t a0, uint32_t a1, uint32_t a2, uint32_t a3,
        uint32_t b0, uint32_t b1) {
    asm volatile(
        "mma.sync.aligned.m16n8k16.row.col.f32.bf16.bf16.f32 "
        "{%0,%1,%2,%3}, {%4,%5,%6,%7}, {%8,%9}, {%0,%1,%2,%3};"
        : "+f"(c[0]), "+f"(c[1]), "+f"(c[2]), "+f"(c[3])
        : "r"(a0), "r"(a1), "r"(a2), "r"(a3), "r"(b0), "r"(b1));
}
static __device__ __forceinline__ void mma16808(float c[4],
        uint32_t a0, uint32_t a1, uint32_t b0) {
    asm volatile(
        "mma.sync.aligned.m16n8k8.row.col.f32.bf16.bf16.f32 "
        "{%0,%1,%2,%3}, {%4,%5}, {%6}, {%0,%1,%2,%3};"
        : "+f"(c[0]), "+f"(c[1]), "+f"(c[2]), "+f"(c[3])
        : "r"(a0), "r"(a1), "r"(b0));
}

static __device__ __forceinline__ void sts32(uint32_t addr, uint32_t v) {
    asm volatile("st.shared.b32 [%0], %1;" :: "r"(addr), "r"(v) : "memory");
}

// ---- G1: dst = relu(src @ W + be), 64x128x128 ----
static __device__ __forceinline__ void gemm_g1(
    uint32_t srcb, uint32_t dstb, const uint32_t (&B)[4][8][2], const float* be,
    int wg, uint32_t lrowoff, uint32_t r_lo, uint32_t khalf,
    uint32_t erow, uint32_t ecolq)
{
    #pragma unroll 1
    for (int mt = 0; mt < 4; mt++) {
        const uint32_t abase = srcb + (uint32_t)mt * 4096 + lrowoff;

        uint32_t af[8][4];
        #pragma unroll
        for (int kc = 0; kc < 8; kc++)
            LDSM4(af[kc][0], af[kc][1], af[kc][2], af[kc][3],
                  abase + ((((uint32_t)(kc * 2) + khalf) ^ r_lo) << 4));

        float c[4][4];
        #pragma unroll
        for (int nt = 0; nt < 4; nt++)
            #pragma unroll
            for (int q = 0; q < 4; q++) c[nt][q] = 0.f;

        #pragma unroll
        for (int kc = 0; kc < 8; kc++)
            #pragma unroll
            for (int nt = 0; nt < 4; nt++)
                mma16816(c[nt], af[kc][0], af[kc][1], af[kc][2], af[kc][3],
                         B[nt][kc][0], B[nt][kc][1]);

        const uint32_t row0 = (uint32_t)mt * 16 + erow;
        const uint32_t dst0 = dstb + row0 * 256;
        #pragma unroll
        for (int nt = 0; nt < 4; nt++) {
            int col = wg * 32 + nt * 8 + (int)ecolq * 2;
            float bea = be[col], beb = be[col + 1];
            float v0 = fmaxf(c[nt][0] + bea, 0.f);
            float v1 = fmaxf(c[nt][1] + beb, 0.f);
            float v2 = fmaxf(c[nt][2] + bea, 0.f);
            float v3 = fmaxf(c[nt][3] + beb, 0.f);
            uint32_t chunk = (uint32_t)(wg * 4 + nt);
            uint32_t a0addr = dst0 + ((chunk ^ erow) << 4) + ecolq * 4;
            sts32(a0addr,        pack_bf16(v0, v1));
            sts32(a0addr + 2048, pack_bf16(v2, v3));
        }
    }
}

// ---- L0: h1 = relu(x @ W0 + be0) via m16n8k8, A from fXS ----
static __device__ __forceinline__ void layer0_mma(
    const float2* xs, uint32_t dstb, const uint32_t (&B0)[4], const float* be0,
    int wg, int lane, uint32_t erow, uint32_t ecolq)
{
    const bool klane = ((lane & 3) == 0);
    #pragma unroll
    for (int mt = 0; mt < 4; mt++) {
        float c[4][4];
        #pragma unroll
        for (int nt = 0; nt < 4; nt++)
            #pragma unroll
            for (int q = 0; q < 4; q++) c[nt][q] = 0.f;

        int ra = mt * 16 + (lane >> 2);
        uint32_t a0 = 0u, a1 = 0u;
        if (klane) {
            float2 xa = xs[ra];
            float2 xb = xs[ra + 8];
            a0 = pack_bf16(xa.x, xa.y);
            a1 = pack_bf16(xb.x, xb.y);
        }
        #pragma unroll
        for (int nt = 0; nt < 4; nt++)
            mma16808(c[nt], a0, a1, B0[nt]);

        const uint32_t row0 = (uint32_t)mt * 16 + erow;
        const uint32_t dst0 = dstb + row0 * 256;
        #pragma unroll
        for (int nt = 0; nt < 4; nt++) {
            int col = wg * 32 + nt * 8 + (int)ecolq * 2;
            float bea = be0[col], beb = be0[col + 1];
            float v0 = fmaxf(c[nt][0] + bea, 0.f);
            float v1 = fmaxf(c[nt][1] + beb, 0.f);
            float v2 = fmaxf(c[nt][2] + bea, 0.f);
            float v3 = fmaxf(c[nt][3] + beb, 0.f);
            uint32_t chunk = (uint32_t)(wg * 4 + nt);
            uint32_t a0addr = dst0 + ((chunk ^ erow) << 4) + ecolq * 4;
            sts32(a0addr,        pack_bf16(v0, v1));
            sts32(a0addr + 2048, pack_bf16(v2, v3));
        }
    }
}

// ---- G2 + fused layer3 dot -> fPPt ----
static __device__ __forceinline__ void gemm_g2(
    uint32_t srcb, const uint32_t (&B)[4][8][2], const float* be,
    const float* w3a, const float* w3b, float2* fPPt,
    int wg, uint32_t lrowoff, uint32_t r_lo, uint32_t khalf,
    uint32_t erow, uint32_t ecolq)
{
    #pragma unroll 1
    for (int mt = 0; mt < 4; mt++) {
        const uint32_t abase = srcb + (uint32_t)mt * 4096 + lrowoff;

        uint32_t af[8][4];
        #pragma unroll
        for (int kc = 0; kc < 8; kc++)
            LDSM4(af[kc][0], af[kc][1], af[kc][2], af[kc][3],
                  abase + ((((uint32_t)(kc * 2) + khalf) ^ r_lo) << 4));

        float c[4][4];
        #pragma unroll
        for (int nt = 0; nt < 4; nt++)
            #pragma unroll
            for (int q = 0; q < 4; q++) c[nt][q] = 0.f;

        #pragma unroll
        for (int kc = 0; kc < 8; kc++)
            #pragma unroll
            for (int nt = 0; nt < 4; nt++)
                mma16816(c[nt], af[kc][0], af[kc][1], af[kc][2], af[kc][3],
                         B[nt][kc][0], B[nt][kc][1]);

        float pA0 = 0.f, pA1 = 0.f, pB0 = 0.f, pB1 = 0.f;
        #pragma unroll
        for (int nt = 0; nt < 4; nt++) {
            int col = wg * 32 + nt * 8 + (int)ecolq * 2;
            float bea = be[col], beb = be[col + 1];
            float wa0 = w3a[col], wa1 = w3a[col + 1];
            float wb0 = w3b[col], wb1 = w3b[col + 1];
            float v0 = fmaxf(c[nt][0] + bea, 0.f);
            float v1 = fmaxf(c[nt][1] + beb, 0.f);
            float v2 = fmaxf(c[nt][2] + bea, 0.f);
            float v3 = fmaxf(c[nt][3] + beb, 0.f);
            pA0 = fmaf(v0, wa0, fmaf(v1, wa1, pA0));
            pA1 = fmaf(v0, wb0, fmaf(v1, wb1, pA1));
            pB0 = fmaf(v2, wa0, fmaf(v3, wa1, pB0));
            pB1 = fmaf(v2, wb0, fmaf(v3, wb1, pB1));
        }
        pA0 += __shfl_xor_sync(0xffffffffu, pA0, 1);
        pA1 += __shfl_xor_sync(0xffffffffu, pA1, 1);
        pB0 += __shfl_xor_sync(0xffffffffu, pB0, 1);
        pB1 += __shfl_xor_sync(0xffffffffu, pB1, 1);
        pA0 += __shfl_xor_sync(0xffffffffu, pA0, 2);
        pA1 += __shfl_xor_sync(0xffffffffu, pA1, 2);
        pB0 += __shfl_xor_sync(0xffffffffu, pB0, 2);
        pB1 += __shfl_xor_sync(0xffffffffu, pB1, 2);
        if (ecolq == 0) {
            int r = mt * 16 + (int)erow;
            fPPt[wg * 64 + r]     = make_float2(pA0, pA1);
            fPPt[wg * 64 + r + 8] = make_float2(pB0, pB1);
        }
    }
}

__global__ void __launch_bounds__(NTHREADS, 2)
ddpm_kernel(const float* __restrict__ noise, const float* __restrict__ z,
            const float* __restrict__ W0, const float* __restrict__ b0,
            const float* __restrict__ W1, const float* __restrict__ b1,
            const float* __restrict__ W2, const float* __restrict__ b2,
            const float* __restrict__ W3, const float* __restrict__ b3,
            const float* __restrict__ E0, const float* __restrict__ E1,
            const float* __restrict__ E2, float* __restrict__ out)
{
    extern __shared__ char smem_raw[];
    const uint32_t sb = smem_u32(smem_raw);
    float* fA = (float*)(smem_raw + SM_F32);
    float2* fXS = (float2*)&fA[F_XS];
    float2* fPP = (float2*)&fA[F_PP];

    const int tid  = threadIdx.x;
    const int lane = tid & 31;
    const int wid  = tid >> 5;
    const bool isWG0 = (wid < 4);
    const int wg   = wid & 3;
    const int base = blockIdx.x * CTA_SAMPLES;

    // ---- prologue ----
    if (tid < 128) {
        fA[F_W3A + tid] = W3[2 * tid];
        fA[F_W3B + tid] = W3[2 * tid + 1];
        fA[F_BE0 + tid] = b0[tid] + E0[99 * NU + tid];  // k=0 (t=99), parity 0
        fA[F_BE1 + tid] = b1[tid] + E1[99 * NU + tid];
        fA[F_BE2 + tid] = b2[tid] + E2[99 * NU + tid];
    }
    if (tid < 192) {
        int smp = base + tid;
        fXS[tid] = (smp < BTOT) ? ((const float2*)noise)[smp] : make_float2(0.f, 0.f);
    }
    if (tid < 2) fA[F_B3 + tid] = b3[tid];
    if (tid == 0) {
        double prod = 1.0;
        for (int t = 0; t < NSTEPS; t++) {
            double xl = -6.0 + 12.0 * (double)t / 99.0;
            double beta = (1.0 / (1.0 + exp(-xl))) * (0.005 - 1e-5) + 1e-5;
            double alpha = 1.0 - beta;
            prod *= alpha;
            fA[F_COEF + t]  = (float)(beta / sqrt(1.0 - prod));
            fA[F_INVAS + t] = (float)(1.0 / sqrt(alpha));
            fA[F_BSQ + t]   = (float)sqrt(beta);
        }
    }

    // ---- weight fragments ----
    uint32_t Bw[4][8][2];
    uint32_t B0f[4] = {0u, 0u, 0u, 0u};
    {
        const float* Wsrc = isWG0 ? W1 : W2;
        const int n0 = wg * 32 + (lane >> 2);
        const int kb2 = (lane & 3) * 2;
        #pragma unroll
        for (int nt = 0; nt < 4; nt++) {
            int n = n0 + nt * 8;
            #pragma unroll
            for (int kc = 0; kc < 8; kc++) {
                int k0 = kc * 16 + kb2;
                Bw[nt][kc][0] = pack_bf16(Wsrc[k0 * NU + n],       Wsrc[(k0 + 1) * NU + n]);
                Bw[nt][kc][1] = pack_bf16(Wsrc[(k0 + 8) * NU + n], Wsrc[(k0 + 9) * NU + n]);
            }
        }
        if (isWG0 && (lane & 3) == 0) {
            #pragma unroll
            for (int nt = 0; nt < 4; nt++) {
                int n = n0 + nt * 8;
                B0f[nt] = pack_bf16(W0[n], W0[NU + n]);
            }
        }
    }

    // per-lane constants
    const uint32_t r_lo    = (uint32_t)(lane & 7);
    const uint32_t half_l  = (uint32_t)((lane >> 3) & 1);
    const uint32_t khalf   = (uint32_t)(lane >> 4);
    const uint32_t lrowoff = (half_l * 8 + r_lo) * 256;
    const uint32_t erow    = (uint32_t)(lane >> 2);
    const uint32_t ecolq   = (uint32_t)(lane & 3);

    __syncthreads();

    if (isWG0) {
        #pragma unroll 1
        for (int k = 0; k < NSTEPS; k++) {
            const int p  = k & 1;
            const int pn = p ^ 1;
            #pragma unroll 1
            for (int i = 0; i < NTILES; i++) {
                if (k > 0) BAR_WAIT256(7 + i * 2 + pn);   // BU[i][(k-1)&1]
                layer0_mma(&fXS[i * 64], sb + SM_H1 + i * 16384, B0f,
                           &fA[F_BE0 + p * 128], wg, lane, erow, ecolq);
                BAR_WG0();
                gemm_g1(sb + SM_H1 + i * 16384, sb + SM_H2 + i * 16384, Bw,
                        &fA[F_BE1 + p * 128], wg, lrowoff, r_lo, khalf, erow, ecolq);
                BAR_ARRIVE256(1 + i * 2 + p);             // BH2[i][p]
            }
        }
    } else {
        const int tid2 = tid - 128;
        const int row  = tid2 & 63;

        #pragma unroll 1
        for (int k = 0; k < NSTEPS; k++) {
            const int p  = k & 1;
            const int pn = p ^ 1;
            const int t  = 99 - k;
            const bool last = (k == NSTEPS - 1);

            #pragma unroll 1
            for (int i = 0; i < NTILES; i++) {
                const int smp = base + i * 64 + row;

                // early global loads: z for this tile; tables at i==0
                float2 zv = make_float2(0.f, 0.f);
                if (tid2 < 64 && smp < BTOT)
                    zv = ((const float2*)z)[(size_t)k * BTOT + smp];
                float be0v = 0.f, be1v = 0.f, be2v = 0.f;
                if (i == 0 && !last) {
                    int tn = t - 1;
                    be0v = b0[tid2] + E0[tn * NU + tid2];
                    be1v = b1[tid2] + E1[tn * NU + tid2];
                    be2v = b2[tid2] + E2[tn * NU + tid2];
                }

                BAR_WAIT256(1 + i * 2 + p);               // BH2[i][p]
                gemm_g2(sb + SM_H2 + i * 16384, Bw, &fA[F_BE2 + p * 128],
                        &fA[F_W3A], &fA[F_W3B], &fPP[i * 256], wg,
                        lrowoff, r_lo, khalf, erow, ecolq);
                if (i == 0 && !last) {                    // publish step-(k+1) tables
                    fA[F_BE0 + pn * 128 + tid2] = be0v;
                    fA[F_BE1 + pn * 128 + tid2] = be1v;
                    fA[F_BE2 + pn * 128 + tid2] = be2v;
                }
                BAR_WG1();
                if (tid2 < 64) {
                    float p0 = fA[F_B3], p1 = fA[F_B3 + 1];
                    #pragma unroll
                    for (int g = 0; g < 4; g++) {
                        float2 v = fPP[i * 256 + g * 64 + row];
                        p0 += v.x; p1 += v.y;
                    }
                    float cf = fA[F_COEF + t], ia = fA[F_INVAS + t], bq = fA[F_BSQ + t];
                    float2 xv = fXS[i * 64 + row];
                    float nx0 = (xv.x - cf * p0) * ia + bq * zv.x;
                    float nx1 = (xv.y - cf * p1) * ia + bq * zv.y;
                    if (last) {
                        if (smp < BTOT) ((float2*)out)[smp] = make_float2(nx0, nx1);
                    } else {
                        fXS[i * 64 + row] = make_float2(nx0, nx1);
                    }
                }
                BAR_ARRIVE256(7 + i * 2 + p);             // BU[i][p]
            }
        }
    }
}

extern "C" void kernel_launch(void* const* d_in, const int* in_sizes, int n_in,
                              void* d_out, int out_size) {
    (void)in_sizes; (void)n_in; (void)out_size;
    const float* noise = (const float*)d_in[0];
    const float* z     = (const float*)d_in[1];
    const float* W0    = (const float*)d_in[2];
    const float* b0    = (const float*)d_in[3];
    const float* W1    = (const float*)d_in[4];
    const float* b1    = (const float*)d_in[5];
    const float* W2    = (const float*)d_in[6];
    const float* b2    = (const float*)d_in[7];
    const float* W3    = (const float*)d_in[8];
    const float* b3    = (const float*)d_in[9];
    const float* E0    = (const float*)d_in[10];
    const float* E1    = (const float*)d_in[11];
    const float* E2    = (const float*)d_in[12];
    float* out = (float*)d_out;

    cudaFuncSetAttribute(ddpm_kernel, cudaFuncAttributeMaxDynamicSharedMemorySize, SMEM_TOTAL);

    dim3 grid((BTOT + CTA_SAMPLES - 1) / CTA_SAMPLES);
    ddpm_kernel<<<grid, NTHREADS, SMEM_TOTAL>>>(noise, z, W0, b0, W1, b1, W2, b2,
                                                W3, b3, E0, E1, E2, out);
}